// round 9
// baseline (speedup 1.0000x reference)
#include <cuda_runtime.h>

// N = 2,000,000 rows. Elementwise Gaussian-splat covariance projection.
// Inputs: rot (N,4) f32, mod (1,) f32, scale (N,2) f32, p_k (N,3) f32,
//         view_matrix (N,16) f32.  Output: A (N,9) f32.
//
// R4 = R2 (best) + register diet:
//   - 2 rows/thread; rot/scale for both rows front-batched (MLP)
//   - vm for row1 loaded AFTER row0 compute retires vm0's registers
//   - __launch_bounds__(256,5) -> <=51 regs -> 62.5% occupancy (was 50%)
//   - streaming load/store hints (single-use data)
//   - p_k loads and output stores staged through smem (coalesced float4)
//   - vm/rot/scale per-thread direct float4 loads (R3 showed smem staging
//     of vm is a LOSS: LDS/STS share the L1TEX pipe, no bytes were wasted)

#define TPB 256
#define RPT 2
#define RPB (TPB * RPT)             // 512 rows per block

__global__ __launch_bounds__(TPB, 5)
void splat_cov_kernel(const float4* __restrict__ rot,       // (N,4) as float4
                      const float*  __restrict__ mod,       // (1,)
                      const float2* __restrict__ scale,     // (N,2) as float2
                      const float*  __restrict__ p_k,       // (N,3)
                      const float4* __restrict__ vm4,       // (N,16) as 4x float4
                      float*        __restrict__ out,       // (N,9)
                      int n)
{
    __shared__ float s_p[RPB * 3];   //  6 KB staged p_k
    __shared__ float s_o[RPB * 9];   // 18 KB staged output

    const int block_base = blockIdx.x * RPB;
    const int rows = min(RPB, n - block_base);

    // ---- Stage p_k cooperatively (coalesced float4, ~1.5 per thread) ----
    {
        const int nfloat = rows * 3;                       // up to 1536
        const float4* src = (const float4*)(p_k + (size_t)block_base * 3);
        float4* dst = (float4*)s_p;
        const int nvec = nfloat >> 2;                      // up to 384
        #pragma unroll 2
        for (int t = threadIdx.x; t < nvec; t += TPB) dst[t] = __ldcs(&src[t]);
        for (int t = (nvec << 2) + threadIdx.x; t < nfloat; t += TPB)
            s_p[t] = p_k[(size_t)block_base * 3 + t];
    }

    const float m = __ldg(mod);

    const int i0 = block_base + threadIdx.x;
    const int i1 = i0 + TPB;
    const bool a0 = i0 < n;
    const bool a1 = i1 < n;

    // ---- Front-batch small per-row loads for both rows (MLP) ----
    float4 q0 = make_float4(0,0,0,0), q1 = make_float4(0,0,0,0);
    float2 sc0 = make_float2(0,0),    sc1 = make_float2(0,0);
    if (a0) { q0 = __ldcs(&rot[i0]); sc0 = __ldcs(&scale[i0]); }
    if (a1) { q1 = __ldcs(&rot[i1]); sc1 = __ldcs(&scale[i1]); }

    // ---- Row 0: vm loads + compute (vm0 registers die at the smem write) ----
    {
        float4 c0, c1, c2, c3;
        if (a0) {
            const float4* v = vm4 + (size_t)i0 * 4;
            c0 = __ldcs(&v[0]); c1 = __ldcs(&v[1]);
            c2 = __ldcs(&v[2]); c3 = __ldcs(&v[3]);
        }
        __syncthreads();   // p_k staged (placed after load issue for overlap)

        if (a0) {
            float r = q0.x, x = q0.y, y = q0.z, z = q0.w;
            float R00 = 1.0f - 2.0f * (y * y + z * z);
            float R10 = 2.0f * (x * y + r * z);
            float R20 = 2.0f * (x * z - r * y);
            float R01 = 2.0f * (x * y - r * z);
            float R11 = 1.0f - 2.0f * (x * x + z * z);
            float R21 = 2.0f * (y * z + r * x);

            float s0 = m * sc0.x, s1 = m * sc0.y;
            float u0 = s0 * R00, u1 = s0 * R10, u2 = s0 * R20;
            float v0 = s1 * R01, v1 = s1 * R11, v2 = s1 * R21;

            float p0 = s_p[threadIdx.x * 3 + 0];
            float p1 = s_p[threadIdx.x * 3 + 1];
            float p2 = s_p[threadIdx.x * 3 + 2];

            float* o = s_o + threadIdx.x * 9;          // odd stride: conflict-free
            o[0] = c0.x * u0 + c1.x * u1 + c2.x * u2;
            o[1] = c0.x * v0 + c1.x * v1 + c2.x * v2;
            o[2] = c0.x * p0 + c1.x * p1 + c2.x * p2 + c3.x;
            o[3] = c0.y * u0 + c1.y * u1 + c2.y * u2;
            o[4] = c0.y * v0 + c1.y * v1 + c2.y * v2;
            o[5] = c0.y * p0 + c1.y * p1 + c2.y * p2 + c3.y;
            o[6] = c0.z * u0 + c1.z * u1 + c2.z * u2;
            o[7] = c0.z * v0 + c1.z * v1 + c2.z * v2;
            o[8] = c0.z * p0 + c1.z * p1 + c2.z * p2 + c3.z;
        }
    }

    // ---- Row 1: vm loads + compute (reuses the retired registers) ----
    {
        float4 c0, c1, c2, c3;
        if (a1) {
            const float4* v = vm4 + (size_t)i1 * 4;
            c0 = __ldcs(&v[0]); c1 = __ldcs(&v[1]);
            c2 = __ldcs(&v[2]); c3 = __ldcs(&v[3]);

            float r = q1.x, x = q1.y, y = q1.z, z = q1.w;
            float R00 = 1.0f - 2.0f * (y * y + z * z);
            float R10 = 2.0f * (x * y + r * z);
            float R20 = 2.0f * (x * z - r * y);
            float R01 = 2.0f * (x * y - r * z);
            float R11 = 1.0f - 2.0f * (x * x + z * z);
            float R21 = 2.0f * (y * z + r * x);

            float s0 = m * sc1.x, s1 = m * sc1.y;
            float u0 = s0 * R00, u1 = s0 * R10, u2 = s0 * R20;
            float v0 = s1 * R01, v1 = s1 * R11, v2 = s1 * R21;

            const int lrow = threadIdx.x + TPB;
            float p0 = s_p[lrow * 3 + 0];
            float p1 = s_p[lrow * 3 + 1];
            float p2 = s_p[lrow * 3 + 2];

            float* o = s_o + lrow * 9;
            o[0] = c0.x * u0 + c1.x * u1 + c2.x * u2;
            o[1] = c0.x * v0 + c1.x * v1 + c2.x * v2;
            o[2] = c0.x * p0 + c1.x * p1 + c2.x * p2 + c3.x;
            o[3] = c0.y * u0 + c1.y * u1 + c2.y * u2;
            o[4] = c0.y * v0 + c1.y * v1 + c2.y * v2;
            o[5] = c0.y * p0 + c1.y * p1 + c2.y * p2 + c3.y;
            o[6] = c0.z * u0 + c1.z * u1 + c2.z * u2;
            o[7] = c0.z * v0 + c1.z * v1 + c2.z * v2;
            o[8] = c0.z * p0 + c1.z * p1 + c2.z * p2 + c3.z;
        }
    }

    __syncthreads();

    // ---- Store cooperatively (coalesced float4 streaming stores) ----
    {
        const int nfloat = rows * 9;                       // up to 4608
        const size_t out_base = (size_t)block_base * 9;    // 4608*blockIdx -> aligned
        float4* dst = (float4*)(out + out_base);
        const float4* src = (const float4*)s_o;
        const int nvec = nfloat >> 2;                      // up to 1152
        #pragma unroll 4
        for (int t = threadIdx.x; t < nvec; t += TPB) __stcs(&dst[t], src[t]);
        for (int t = (nvec << 2) + threadIdx.x; t < nfloat; t += TPB)
            out[out_base + t] = s_o[t];
    }
}

extern "C" void kernel_launch(void* const* d_in, const int* in_sizes, int n_in,
                              void* d_out, int out_size)
{
    const float4* rot   = (const float4*)d_in[0];
    const float*  mod   = (const float*)d_in[1];
    const float2* scale = (const float2*)d_in[2];
    const float*  p_k   = (const float*)d_in[3];
    const float4* vm4   = (const float4*)d_in[4];
    float* out = (float*)d_out;

    int n = in_sizes[0] / 4;   // rot has N*4 elements

    int blocks = (n + RPB - 1) / RPB;
    splat_cov_kernel<<<blocks, TPB>>>(rot, mod, scale, p_k, vm4, out, n);
}

// round 10
// speedup vs baseline: 1.2257x; 1.2257x over previous
#include <cuda_runtime.h>

// N = 2,000,000 rows. Elementwise Gaussian-splat covariance projection.
// Inputs: rot (N,4) f32, mod (1,) f32, scale (N,2) f32, p_k (N,3) f32,
//         view_matrix (N,16) f32.  Output: A (N,9) f32.
//
// R5 = R3 (best: RPT=2 front-batched, p_k/out staged via smem) with
// TPB=128 so 64-reg threads pack 8 CTAs/SM (50% occ, 8 overlapping
// barrier domains) instead of 4.
//   - NO cache hints (__ldcs experiments regressed)
//   - NO reg caps below 64 (launch_bounds(_,5) caused spills -> L1 flood)

#define TPB 128
#define RPT 2
#define RPB (TPB * RPT)             // 256 rows per block

__global__ __launch_bounds__(TPB, 8)
void splat_cov_kernel(const float4* __restrict__ rot,       // (N,4) as float4
                      const float*  __restrict__ mod,       // (1,)
                      const float2* __restrict__ scale,     // (N,2) as float2
                      const float*  __restrict__ p_k,       // (N,3)
                      const float4* __restrict__ vm4,       // (N,16) as 4x float4
                      float*        __restrict__ out,       // (N,9)
                      int n)
{
    __shared__ float s_p[RPB * 3];   //  3 KB staged p_k
    __shared__ float s_o[RPB * 9];   //  9 KB staged output

    const int block_base = blockIdx.x * RPB;
    const int rows = min(RPB, n - block_base);

    // ---- Stage p_k cooperatively: coalesced float4 loads ----
    {
        const int nfloat = rows * 3;                       // up to 768
        // block_base*3 = 768*blockIdx -> float4 aligned
        const float4* src = (const float4*)(p_k + (size_t)block_base * 3);
        float4* dst = (float4*)s_p;
        const int nvec = nfloat >> 2;                      // up to 192
        #pragma unroll 2
        for (int t = threadIdx.x; t < nvec; t += TPB) dst[t] = src[t];
        for (int t = (nvec << 2) + threadIdx.x; t < nfloat; t += TPB)
            s_p[t] = p_k[(size_t)block_base * 3 + t];
    }

    const float m = __ldg(mod);

    int idx[RPT];
    bool act[RPT];
    #pragma unroll
    for (int k = 0; k < RPT; k++) {
        idx[k] = block_base + threadIdx.x + k * TPB;
        act[k] = idx[k] < n;
    }

    // ---- Front-batch ALL global loads (maximize MLP) ----
    float4 q[RPT];
    float2 sc[RPT];
    float4 c0[RPT], c1[RPT], c2[RPT], c3[RPT];
    #pragma unroll
    for (int k = 0; k < RPT; k++) {
        if (act[k]) {
            q[k]  = rot[idx[k]];
            sc[k] = scale[idx[k]];
            const float4* v = vm4 + (size_t)idx[k] * 4;
            c0[k] = v[0]; c1[k] = v[1]; c2[k] = v[2]; c3[k] = v[3];
        }
    }

    __syncthreads();   // p_k staged

    #pragma unroll
    for (int k = 0; k < RPT; k++) {
        if (!act[k]) continue;

        float r = q[k].x, x = q[k].y, y = q[k].z, z = q[k].w;

        float R00 = 1.0f - 2.0f * (y * y + z * z);
        float R10 = 2.0f * (x * y + r * z);
        float R20 = 2.0f * (x * z - r * y);
        float R01 = 2.0f * (x * y - r * z);
        float R11 = 1.0f - 2.0f * (x * x + z * z);
        float R21 = 2.0f * (y * z + r * x);

        float s0 = m * sc[k].x;
        float s1 = m * sc[k].y;

        float u0 = s0 * R00, u1 = s0 * R10, u2 = s0 * R20;
        float v0 = s1 * R01, v1 = s1 * R11, v2 = s1 * R21;

        const int lrow = threadIdx.x + k * TPB;            // local row in block
        float p0 = s_p[lrow * 3 + 0];
        float p1 = s_p[lrow * 3 + 1];
        float p2 = s_p[lrow * 3 + 2];

        float* o = s_o + lrow * 9;                         // odd stride: conflict-free
        o[0] = c0[k].x * u0 + c1[k].x * u1 + c2[k].x * u2;
        o[1] = c0[k].x * v0 + c1[k].x * v1 + c2[k].x * v2;
        o[2] = c0[k].x * p0 + c1[k].x * p1 + c2[k].x * p2 + c3[k].x;
        o[3] = c0[k].y * u0 + c1[k].y * u1 + c2[k].y * u2;
        o[4] = c0[k].y * v0 + c1[k].y * v1 + c2[k].y * v2;
        o[5] = c0[k].y * p0 + c1[k].y * p1 + c2[k].y * p2 + c3[k].y;
        o[6] = c0[k].z * u0 + c1[k].z * u1 + c2[k].z * u2;
        o[7] = c0[k].z * v0 + c1[k].z * v1 + c2[k].z * v2;
        o[8] = c0[k].z * p0 + c1[k].z * p1 + c2[k].z * p2 + c3[k].z;
    }

    __syncthreads();   // outputs staged

    // ---- Store cooperatively: coalesced float4 stores ----
    {
        const int nfloat = rows * 9;                       // up to 2304
        const size_t out_base = (size_t)block_base * 9;    // 2304*blockIdx -> aligned
        float4* dst = (float4*)(out + out_base);
        const float4* src = (const float4*)s_o;
        const int nvec = nfloat >> 2;                      // up to 576
        #pragma unroll 4
        for (int t = threadIdx.x; t < nvec; t += TPB) dst[t] = src[t];
        for (int t = (nvec << 2) + threadIdx.x; t < nfloat; t += TPB)
            out[out_base + t] = s_o[t];
    }
}

extern "C" void kernel_launch(void* const* d_in, const int* in_sizes, int n_in,
                              void* d_out, int out_size)
{
    const float4* rot   = (const float4*)d_in[0];
    const float*  mod   = (const float*)d_in[1];
    const float2* scale = (const float2*)d_in[2];
    const float*  p_k   = (const float*)d_in[3];
    const float4* vm4   = (const float4*)d_in[4];
    float* out = (float*)d_out;

    int n = in_sizes[0] / 4;   // rot has N*4 elements

    int blocks = (n + RPB - 1) / RPB;
    splat_cov_kernel<<<blocks, TPB>>>(rot, mod, scale, p_k, vm4, out, n);
}